// round 11
// baseline (speedup 1.0000x reference)
#include <cuda_runtime.h>

#define THREADS 512
#define ITEMS 16
#define TILE (THREADS * ITEMS)   // 8192
#define MAX_TILES 8192
#define STRIDE 16                 // 16 x u64 = 128 B per state entry (own cache line)
#define SIDX(i) ((i) + ((i) >> 4))   // smem skew: conflict-free blocked writes

// decoupled-lookback state, ONE PER 128B CACHE LINE to kill L2 sector camping:
// high 32 bits = epoch*4 + status (1=aggregate, 2=prefix), low 32 = fp32 bits.
// Epoch versioning => no init kernel (stale lines decode invalid this epoch).
// Atomic publish/poll (immediate L2 visibility — load-based polling measured +35%).
__device__ unsigned long long g_state[MAX_TILES * STRIDE];
__device__ unsigned int g_ticket;   // zero-init once; monotonic across graph replays

__device__ __forceinline__ unsigned long long pack_sv(unsigned st, float v) {
    return ((unsigned long long)st << 32) | (unsigned long long)__float_as_uint(v);
}

// pure-ALU 5-entry LUT: no shared-memory gather, no bank conflicts
__device__ __forceinline__ float lut5(int c, float t1, float t2, float t3,
                                      float t4, float t5) {
    float a = (c < 2) ? t1 : ((c < 3) ? t2 : t3);   // c == 1,2,3
    float b = (c < 5) ? t4 : t5;                     // c == 4,5
    return (c < 4) ? a : b;
}

__global__ void __launch_bounds__(THREADS, 1) rtam_scan(
    const int* __restrict__ ann,
    const float* __restrict__ p_origin,
    const float* __restrict__ p_bd,
    const float* __restrict__ p_d,
    const float* __restrict__ p_s,
    const float* __restrict__ p_inc,
    const float* __restrict__ p_bi,
    float* __restrict__ out,
    int n, int ntiles)
{
    __shared__ float s_out[TILE + TILE / 16];   // skewed
    __shared__ float s_table[8];
    __shared__ float s_warp[THREADS / 32];
    __shared__ float s_excl;
    __shared__ unsigned s_ticket;

    const int tid  = threadIdx.x;
    const int lane = tid & 31;
    const int wid  = tid >> 5;

    if (tid == 0) {
        s_ticket = atomicAdd(&g_ticket, 1u);
        const float EPS = 0.05f;
        float bd = *p_bd, d = *p_d, s = *p_s, inc = *p_inc, bi = *p_bi;
        s_table[0] = 0.f;
        s_table[1] = fminf(bd, fminf(0.f, d)) - EPS;                 // big decrease
        s_table[2] = fminf(fmaxf(d, bd + EPS), -EPS);                // decrease (clip)
        s_table[3] = s;                                              // same
        s_table[4] = fminf(fmaxf(inc, EPS), bi - EPS);               // increase (clip)
        s_table[5] = fmaxf(bi, fmaxf(0.f, inc) + EPS);               // big increase
        s_table[6] = *p_origin;
    }
    __syncthreads();

    const unsigned ticket = s_ticket;
    const unsigned tile   = ticket % (unsigned)ntiles;
    const unsigned eb     = (ticket / (unsigned)ntiles) * 4u;   // epoch status base
    const float origin  = s_table[6];
    // table values into registers once; broadcast LDS, conflict-free
    const float t1 = s_table[1], t2 = s_table[2], t3 = s_table[3];
    const float t4 = s_table[4], t5 = s_table[5];

    const long long base = (long long)tile * TILE;
    const long long rem64 = (long long)n - base;
    const int remaining = (rem64 > (long long)TILE) ? TILE : (int)rem64;

    // ---- per-thread blocked load + serial inclusive scan (16 items) ----
    float vals[ITEMS];
    float run = 0.f;

    if (remaining >= TILE) {
        const int4* in4 = (const int4*)(ann + base);
        #pragma unroll
        for (int k = 0; k < ITEMS / 4; k++) {
            int4 c = in4[tid * (ITEMS / 4) + k];
            run += lut5(c.x, t1, t2, t3, t4, t5); vals[4 * k + 0] = run;
            run += lut5(c.y, t1, t2, t3, t4, t5); vals[4 * k + 1] = run;
            run += lut5(c.z, t1, t2, t3, t4, t5); vals[4 * k + 2] = run;
            run += lut5(c.w, t1, t2, t3, t4, t5); vals[4 * k + 3] = run;
        }
    } else {
        #pragma unroll
        for (int j = 0; j < ITEMS; j++) {
            long long idx = base + (long long)tid * ITEMS + j;
            float c = 0.f;
            if (idx < (long long)n) c = lut5(ann[idx], t1, t2, t3, t4, t5);
            run += c;
            vals[j] = run;
        }
    }

    // ---- block scan of per-thread sums (warp shfl + smem across 16 warps) ----
    const float tsum = run;
    float x = tsum;
    #pragma unroll
    for (int o = 1; o < 32; o <<= 1) {
        float y = __shfl_up_sync(0xFFFFFFFFu, x, o);
        if (lane >= o) x += y;
    }
    if (lane == 31) s_warp[wid] = x;
    __syncthreads();
    if (wid == 0) {
        float w = (lane < THREADS / 32) ? s_warp[lane] : 0.f;
        #pragma unroll
        for (int o = 1; o < THREADS / 32; o <<= 1) {
            float y = __shfl_up_sync(0xFFFFFFFFu, w, o);
            if (lane >= o) w += y;
        }
        if (lane < THREADS / 32) s_warp[lane] = w;
    }
    __syncthreads();

    const float block_agg   = s_warp[THREADS / 32 - 1];
    const float thread_excl = (wid > 0 ? s_warp[wid - 1] : 0.f) + (x - tsum);

    // ---- warp 0: publish aggregate, decoupled lookback, publish prefix ----
    if (wid == 0) {
        if (lane == 0)
            atomicExch(&g_state[tile * STRIDE],
                       pack_sv(eb + (tile == 0 ? 2u : 1u), block_agg));

        float excl = 0.f;
        if (tile > 0) {
            int look = (int)tile - 1;
            for (;;) {
                int idx = look - lane;
                unsigned d; float val;
                if (idx >= 0) {
                    unsigned long long v = atomicAdd(&g_state[idx * STRIDE], 0ULL);
                    d   = (unsigned)(v >> 32) - eb;   // stale epoch -> huge -> invalid
                    val = __uint_as_float((unsigned)(v & 0xFFFFFFFFULL));
                } else {
                    d = 2u; val = 0.f;
                }
                unsigned pm = __ballot_sync(0xFFFFFFFFu, d == 2u);
                unsigned am = __ballot_sync(0xFFFFFFFFu, d == 1u || d == 2u);
                if (pm) {
                    int p = __ffs(pm) - 1;   // closest predecessor with a full prefix
                    unsigned need = (p == 31) ? 0xFFFFFFFFu : ((1u << (p + 1)) - 1u);
                    if ((am & need) == need) {
                        float contrib = (lane <= p) ? val : 0.f;
                        #pragma unroll
                        for (int o = 16; o; o >>= 1)
                            contrib += __shfl_xor_sync(0xFFFFFFFFu, contrib, o);
                        excl += contrib;
                        break;
                    }
                } else if (am == 0xFFFFFFFFu) {
                    float contrib = val;     // window of 32 aggregates, keep walking
                    #pragma unroll
                    for (int o = 16; o; o >>= 1)
                        contrib += __shfl_xor_sync(0xFFFFFFFFu, contrib, o);
                    excl += contrib;
                    look -= 32;
                }
                // else: spin until predecessors publish
            }
            if (lane == 0)
                atomicExch(&g_state[tile * STRIDE], pack_sv(eb + 2u, excl + block_agg));
        }
        if (lane == 0) s_excl = excl;
    }

    // ---- stage tile-local results to skewed smem (overlaps lookback) ----
    #pragma unroll
    for (int j = 0; j < ITEMS; j++)
        s_out[SIDX(tid * ITEMS + j)] = thread_excl + vals[j];
    __syncthreads();

    const float ofs = origin + s_excl;

    // ---- coalesced, aligned store of out[base+1 .. base+remaining] ----
    if (remaining >= TILE) {
        float* op = out + base;                 // 16B-aligned (base % 8192 == 0)
        if (tid < 3)  op[1 + tid] = ofs + s_out[SIDX(tid)];       // head: out[base+1..3]
        if (tid == 3) op[TILE]    = ofs + s_out[SIDX(TILE - 1)];  // tail: out[base+TILE]
        float4* o4 = (float4*)(op + 4);         // 16B-aligned
        const int NV = (TILE - 4) / 4;          // 2047 vectors covering smem i = 3..8190
        for (int v = tid; v < NV; v += THREADS) {
            int i = 3 + 4 * v;
            float4 r;
            r.x = ofs + s_out[SIDX(i + 0)];
            r.y = ofs + s_out[SIDX(i + 1)];
            r.z = ofs + s_out[SIDX(i + 2)];
            r.w = ofs + s_out[SIDX(i + 3)];
            o4[v] = r;
        }
    } else {
        for (int i = tid; i < remaining; i += THREADS)
            out[base + 1 + i] = ofs + s_out[SIDX(i)];
    }

    if (tile == 0 && tid == 0) out[0] = origin;
}

extern "C" void kernel_launch(void* const* d_in, const int* in_sizes, int n_in,
                              void* d_out, int out_size) {
    const int*   ann    = (const int*)d_in[0];
    const float* origin = (const float*)d_in[1];
    const float* bd     = (const float*)d_in[2];
    const float* d      = (const float*)d_in[3];
    const float* s      = (const float*)d_in[4];
    const float* inc    = (const float*)d_in[5];
    const float* bi     = (const float*)d_in[6];
    float* out = (float*)d_out;

    int n = in_sizes[0];
    int ntiles = (n + TILE - 1) / TILE;
    if (ntiles > MAX_TILES) ntiles = MAX_TILES;   // n = 2^25 -> 4096 tiles

    rtam_scan<<<ntiles, THREADS>>>(ann, origin, bd, d, s, inc, bi, out, n, ntiles);
}

// round 12
// speedup vs baseline: 1.1048x; 1.1048x over previous
#include <cuda_runtime.h>

#define MAX_N   33554432              // 2^25 (reference size); scratch sized for this
#define THREADS 512
#define ITEMS   32
#define TILE    (THREADS * ITEMS)     // 16384
#define MAX_TILES ((MAX_N + TILE - 1) / TILE)   // 2048

// Scratch: byte-packed codes (4 codes/u32) + per-tile partial sums.
// Static __device__ arrays = sanctioned scratch (no allocation APIs).
__device__ unsigned g_packed[MAX_N / 4];       // 32 MB
__device__ float    g_part[MAX_TILES + 32];

// pure-ALU 5-entry LUT (codes 1..5)
__device__ __forceinline__ float lut5(int c, float t1, float t2, float t3,
                                      float t4, float t5) {
    float a = (c < 2) ? t1 : ((c < 3) ? t2 : t3);
    float b = (c < 5) ? t4 : t5;
    return (c < 4) ? a : b;
}
// 0 -> 0.0 variant for out-of-bounds padding codes
__device__ __forceinline__ float lut6(int c, float t1, float t2, float t3,
                                      float t4, float t5) {
    return c ? lut5(c, t1, t2, t3, t4, t5) : 0.f;
}

__device__ __forceinline__ void make_table(const float* p_bd, const float* p_d,
                                           const float* p_s, const float* p_inc,
                                           const float* p_bi, float* tbl) {
    const float EPS = 0.05f;
    float bd = *p_bd, d = *p_d, s = *p_s, inc = *p_inc, bi = *p_bi;
    tbl[0] = fminf(bd, fminf(0.f, d)) - EPS;          // 1: big decrease
    tbl[1] = fminf(fmaxf(d, bd + EPS), -EPS);         // 2: decrease (clip)
    tbl[2] = s;                                       // 3: same
    tbl[3] = fminf(fmaxf(inc, EPS), bi - EPS);        // 4: increase (clip)
    tbl[4] = fmaxf(bi, fmaxf(0.f, inc) + EPS);        // 5: big increase
}

// ---------------- Kernel A: per-tile reduce + byte-pack codes ----------------
__global__ void __launch_bounds__(THREADS) rtam_reduce(
    const int* __restrict__ ann,
    const float* __restrict__ p_bd, const float* __restrict__ p_d,
    const float* __restrict__ p_s,  const float* __restrict__ p_inc,
    const float* __restrict__ p_bi,
    int n)
{
    __shared__ float s_tbl[5];
    __shared__ float s_warp[THREADS / 32];

    const int tid  = threadIdx.x;
    const int lane = tid & 31;
    const int wid  = tid >> 5;
    const int tile = blockIdx.x;

    if (tid == 0) make_table(p_bd, p_d, p_s, p_inc, p_bi, s_tbl);
    __syncthreads();
    const float t1 = s_tbl[0], t2 = s_tbl[1], t3 = s_tbl[2],
                t4 = s_tbl[3], t5 = s_tbl[4];

    const long long base = (long long)tile * TILE;
    const bool full = (base + TILE <= (long long)n);

    unsigned pk[8];
    float run = 0.f;

    if (full) {
        const int4* in4 = (const int4*)(ann + base);
        #pragma unroll
        for (int k = 0; k < 8; k++) {
            int4 c = in4[tid * 8 + k];
            pk[k] = (unsigned)c.x | ((unsigned)c.y << 8) |
                    ((unsigned)c.z << 16) | ((unsigned)c.w << 24);
            run += lut5(c.x, t1, t2, t3, t4, t5);
            run += lut5(c.y, t1, t2, t3, t4, t5);
            run += lut5(c.z, t1, t2, t3, t4, t5);
            run += lut5(c.w, t1, t2, t3, t4, t5);
        }
    } else {
        #pragma unroll
        for (int k = 0; k < 8; k++) {
            unsigned p = 0;
            #pragma unroll
            for (int b = 0; b < 4; b++) {
                long long idx = base + (long long)tid * ITEMS + k * 4 + b;
                int c = (idx < (long long)n) ? ann[idx] : 0;
                p |= (unsigned)c << (8 * b);
                run += lut6(c, t1, t2, t3, t4, t5);
            }
            pk[k] = p;
        }
    }

    // store packed codes: 2x STG.128 per thread, fully coalesced
    uint4* pp = (uint4*)g_packed + (long long)tile * (TILE / 16) + tid * 2;
    pp[0] = make_uint4(pk[0], pk[1], pk[2], pk[3]);
    pp[1] = make_uint4(pk[4], pk[5], pk[6], pk[7]);

    // block reduce of per-thread sums
    #pragma unroll
    for (int o = 16; o; o >>= 1) run += __shfl_xor_sync(0xFFFFFFFFu, run, o);
    if (lane == 0) s_warp[wid] = run;
    __syncthreads();
    if (wid == 0) {
        float v = (lane < THREADS / 32) ? s_warp[lane] : 0.f;
        #pragma unroll
        for (int o = 8; o; o >>= 1) v += __shfl_xor_sync(0xFFFFFFFFu, v, o);
        if (lane == 0) g_part[tile] = v;
    }
}

// ---------------- Kernel B: exclusive scan of tile partials (1 block) --------
#define BTHREADS 1024
__global__ void __launch_bounds__(BTHREADS) rtam_mid(int ntiles) {
    __shared__ float s_warp[BTHREADS / 32];
    const int tid  = threadIdx.x;
    const int lane = tid & 31;
    const int wid  = tid >> 5;
    const int K = (ntiles + BTHREADS - 1) / BTHREADS;   // 2 for 2048 tiles

    float v[8];                         // supports ntiles <= 8192
    float run = 0.f;
    for (int j = 0; j < K; j++) {
        int idx = tid * K + j;
        float p = (idx < ntiles) ? g_part[idx] : 0.f;
        v[j] = run;                     // exclusive within thread
        run += p;
    }

    float x = run;
    #pragma unroll
    for (int o = 1; o < 32; o <<= 1) {
        float y = __shfl_up_sync(0xFFFFFFFFu, x, o);
        if (lane >= o) x += y;
    }
    if (lane == 31) s_warp[wid] = x;
    __syncthreads();
    if (wid == 0) {
        float w = (lane < BTHREADS / 32) ? s_warp[lane] : 0.f;
        #pragma unroll
        for (int o = 1; o < BTHREADS / 32; o <<= 1) {
            float y = __shfl_up_sync(0xFFFFFFFFu, w, o);
            if (lane >= o) w += y;
        }
        if (lane < BTHREADS / 32) s_warp[lane] = w;
    }
    __syncthreads();

    const float excl = (wid > 0 ? s_warp[wid - 1] : 0.f) + (x - run);
    for (int j = 0; j < K; j++) {
        int idx = tid * K + j;
        if (idx < ntiles) g_part[idx] = excl + v[j];
    }
}

// ---------------- Kernel C: rebuild scan from packed codes + store -----------
__global__ void __launch_bounds__(THREADS) rtam_store(
    const int* __restrict__ ann,
    const float* __restrict__ p_origin,
    const float* __restrict__ p_bd, const float* __restrict__ p_d,
    const float* __restrict__ p_s,  const float* __restrict__ p_inc,
    const float* __restrict__ p_bi,
    float* __restrict__ out,
    int n)
{
    __shared__ float s_tbl[6];
    __shared__ float s_warp[THREADS / 32];

    const int tid  = threadIdx.x;
    const int lane = tid & 31;
    const int wid  = tid >> 5;
    const int tile = blockIdx.x;

    if (tid == 0) {
        make_table(p_bd, p_d, p_s, p_inc, p_bi, s_tbl);
        s_tbl[5] = *p_origin;
    }
    __syncthreads();
    const float t1 = s_tbl[0], t2 = s_tbl[1], t3 = s_tbl[2],
                t4 = s_tbl[3], t5 = s_tbl[4];
    const float origin = s_tbl[5];

    const long long base = (long long)tile * TILE;
    const long long rem64 = (long long)n - base;
    const int remaining = (rem64 > (long long)TILE) ? TILE : (int)rem64;
    const bool full = (remaining >= TILE);

    // load packed codes: 2x LDG.128
    const uint4* pp = (const uint4*)g_packed + (long long)tile * (TILE / 16) + tid * 2;
    uint4 a = pp[0], b = pp[1];
    unsigned pk[8] = {a.x, a.y, a.z, a.w, b.x, b.y, b.z, b.w};

    // per-thread sum (codes may contain 0 padding only in the partial tile)
    float run = 0.f;
    #pragma unroll
    for (int k = 0; k < 8; k++) {
        unsigned p = pk[k];
        run += lut6((int)(p       & 0xFF), t1, t2, t3, t4, t5);
        run += lut6((int)((p>> 8) & 0xFF), t1, t2, t3, t4, t5);
        run += lut6((int)((p>>16) & 0xFF), t1, t2, t3, t4, t5);
        run += lut6((int)((p>>24) & 0xFF), t1, t2, t3, t4, t5);
    }

    // block scan of per-thread sums
    const float tsum = run;
    float x = tsum;
    #pragma unroll
    for (int o = 1; o < 32; o <<= 1) {
        float y = __shfl_up_sync(0xFFFFFFFFu, x, o);
        if (lane >= o) x += y;
    }
    if (lane == 31) s_warp[wid] = x;
    __syncthreads();
    if (wid == 0) {
        float w = (lane < THREADS / 32) ? s_warp[lane] : 0.f;
        #pragma unroll
        for (int o = 1; o < THREADS / 32; o <<= 1) {
            float y = __shfl_up_sync(0xFFFFFFFFu, w, o);
            if (lane >= o) w += y;
        }
        if (lane < THREADS / 32) s_warp[lane] = w;
    }
    __syncthreads();

    const float thread_excl = (wid > 0 ? s_warp[wid - 1] : 0.f) + (x - tsum);
    // pref == out[base + 32*tid] (origin + cross-tile exclusive + in-tile exclusive)
    const float pref = origin + g_part[tile] + thread_excl;

    if (full) {
        float4* o4 = (float4*)(out + base + tid * ITEMS);   // 16B-aligned
        float acc = 0.f;
        #pragma unroll
        for (int k = 0; k < 8; k++) {
            unsigned p = pk[k];
            float4 r;
            r.x = pref + acc; acc += lut5((int)(p       & 0xFF), t1, t2, t3, t4, t5);
            r.y = pref + acc; acc += lut5((int)((p>> 8) & 0xFF), t1, t2, t3, t4, t5);
            r.z = pref + acc; acc += lut5((int)((p>>16) & 0xFF), t1, t2, t3, t4, t5);
            r.w = pref + acc; acc += lut5((int)((p>>24) & 0xFF), t1, t2, t3, t4, t5);
            o4[k] = r;
        }
        if (tid == THREADS - 1 && base + TILE == (long long)n)
            out[n] = pref + acc;          // out[n] from the last full tile
    } else {
        float acc = 0.f;
        for (int j = 0; j < ITEMS; j++) {
            int i = tid * ITEMS + j;
            if (i <= remaining) out[base + i] = pref + acc;
            int c = (int)((pk[j >> 2] >> (8 * (j & 3))) & 0xFF);
            acc += lut6(c, t1, t2, t3, t4, t5);
        }
    }
    // out[0] comes from tile 0 / tid 0 / first slot (pref == origin there).
}

extern "C" void kernel_launch(void* const* d_in, const int* in_sizes, int n_in,
                              void* d_out, int out_size) {
    const int*   ann    = (const int*)d_in[0];
    const float* origin = (const float*)d_in[1];
    const float* bd     = (const float*)d_in[2];
    const float* d      = (const float*)d_in[3];
    const float* s      = (const float*)d_in[4];
    const float* inc    = (const float*)d_in[5];
    const float* bi     = (const float*)d_in[6];
    float* out = (float*)d_out;

    int n = in_sizes[0];
    if (n > MAX_N) n = MAX_N;                       // scratch capacity (ref: n == 2^25)
    int ntiles = (n + TILE - 1) / TILE;             // 2048 for 2^25

    rtam_reduce<<<ntiles, THREADS>>>(ann, bd, d, s, inc, bi, n);
    rtam_mid<<<1, BTHREADS>>>(ntiles);
    rtam_store<<<ntiles, THREADS>>>(ann, origin, bd, d, s, inc, bi, out, n);
}

// round 13
// speedup vs baseline: 1.4628x; 1.3241x over previous
#include <cuda_runtime.h>

#define THREADS 512
#define ITEMS 16
#define TILE (THREADS * ITEMS)   // 8192
#define MAX_TILES 65536

// decoupled-lookback state: high 32 bits = epoch*4 + status (1=aggregate, 2=prefix),
// low 32 bits = fp32 value bits. One 64-bit atomic word => no fence needed.
// Epoch versioning => NO init kernel: stale words from the previous graph replay
// decode as invalid for the current epoch. Atomic publish/poll is the fast path
// on this chip (ld.cg polling measured +35% slower; 128B-padded state +48% slower).
__device__ unsigned long long g_state[MAX_TILES];
__device__ unsigned int g_ticket;   // zero-init once; monotonic across graph replays

__device__ __forceinline__ unsigned long long pack_sv(unsigned st, float v) {
    return ((unsigned long long)st << 32) | (unsigned long long)__float_as_uint(v);
}

// pure-ALU 5-entry LUT: no shared-memory gather, no bank conflicts
__device__ __forceinline__ float lut5(int c, float t1, float t2, float t3,
                                      float t4, float t5) {
    float a = (c < 2) ? t1 : ((c < 3) ? t2 : t3);   // c == 1,2,3
    float b = (c < 5) ? t4 : t5;                     // c == 4,5
    return (c < 4) ? a : b;
}

#define SIDX(i) ((i) + ((i) >> 4))   // smem skew: conflict-free blocked writes

__global__ void __launch_bounds__(THREADS, 1) rtam_scan(
    const int* __restrict__ ann,
    const float* __restrict__ p_origin,
    const float* __restrict__ p_bd,
    const float* __restrict__ p_d,
    const float* __restrict__ p_s,
    const float* __restrict__ p_inc,
    const float* __restrict__ p_bi,
    float* __restrict__ out,
    int n, int ntiles)
{
    __shared__ float s_out[TILE + TILE / 16];   // skewed
    __shared__ float s_table[8];
    __shared__ float s_warp[THREADS / 32];
    __shared__ float s_excl;
    __shared__ unsigned s_ticket;

    const int tid  = threadIdx.x;
    const int lane = tid & 31;
    const int wid  = tid >> 5;

    if (tid == 0) {
        s_ticket = atomicAdd(&g_ticket, 1u);
        const float EPS = 0.05f;
        float bd = *p_bd, d = *p_d, s = *p_s, inc = *p_inc, bi = *p_bi;
        s_table[0] = 0.f;
        s_table[1] = fminf(bd, fminf(0.f, d)) - EPS;                 // big decrease
        s_table[2] = fminf(fmaxf(d, bd + EPS), -EPS);                // decrease (clip)
        s_table[3] = s;                                              // same
        s_table[4] = fminf(fmaxf(inc, EPS), bi - EPS);               // increase (clip)
        s_table[5] = fmaxf(bi, fmaxf(0.f, inc) + EPS);               // big increase
        s_table[6] = *p_origin;
    }
    __syncthreads();

    const unsigned ticket = s_ticket;
    const unsigned tile   = ticket % (unsigned)ntiles;
    const unsigned eb     = (ticket / (unsigned)ntiles) * 4u;   // epoch status base
    const float origin  = s_table[6];
    // table values into registers once; broadcast LDS, conflict-free
    const float t1 = s_table[1], t2 = s_table[2], t3 = s_table[3];
    const float t4 = s_table[4], t5 = s_table[5];

    const long long base = (long long)tile * TILE;
    const long long rem64 = (long long)n - base;
    const int remaining = (rem64 > (long long)TILE) ? TILE : (int)rem64;

    // ---- per-thread blocked load + serial inclusive scan (16 items) ----
    float vals[ITEMS];
    float run = 0.f;

    if (remaining >= TILE) {
        const int4* in4 = (const int4*)(ann + base);
        #pragma unroll
        for (int k = 0; k < ITEMS / 4; k++) {
            int4 c = in4[tid * (ITEMS / 4) + k];
            run += lut5(c.x, t1, t2, t3, t4, t5); vals[4 * k + 0] = run;
            run += lut5(c.y, t1, t2, t3, t4, t5); vals[4 * k + 1] = run;
            run += lut5(c.z, t1, t2, t3, t4, t5); vals[4 * k + 2] = run;
            run += lut5(c.w, t1, t2, t3, t4, t5); vals[4 * k + 3] = run;
        }
    } else {
        #pragma unroll
        for (int j = 0; j < ITEMS; j++) {
            long long idx = base + (long long)tid * ITEMS + j;
            float c = 0.f;
            if (idx < (long long)n) c = lut5(ann[idx], t1, t2, t3, t4, t5);
            run += c;
            vals[j] = run;
        }
    }

    // ---- block scan of per-thread sums (warp shfl + smem across 16 warps) ----
    const float tsum = run;
    float x = tsum;
    #pragma unroll
    for (int o = 1; o < 32; o <<= 1) {
        float y = __shfl_up_sync(0xFFFFFFFFu, x, o);
        if (lane >= o) x += y;
    }
    if (lane == 31) s_warp[wid] = x;
    __syncthreads();
    if (wid == 0) {
        float w = (lane < THREADS / 32) ? s_warp[lane] : 0.f;
        #pragma unroll
        for (int o = 1; o < THREADS / 32; o <<= 1) {
            float y = __shfl_up_sync(0xFFFFFFFFu, w, o);
            if (lane >= o) w += y;
        }
        if (lane < THREADS / 32) s_warp[lane] = w;
    }
    __syncthreads();

    const float block_agg   = s_warp[THREADS / 32 - 1];
    const float thread_excl = (wid > 0 ? s_warp[wid - 1] : 0.f) + (x - tsum);

    // ---- warp 0: publish aggregate, decoupled lookback, publish prefix ----
    if (wid == 0) {
        if (lane == 0)
            atomicExch(&g_state[tile], pack_sv(eb + (tile == 0 ? 2u : 1u), block_agg));

        float excl = 0.f;
        if (tile > 0) {
            int look = (int)tile - 1;
            for (;;) {
                int idx = look - lane;
                unsigned d; float val;
                if (idx >= 0) {
                    unsigned long long v = atomicAdd(&g_state[idx], 0ULL);
                    d   = (unsigned)(v >> 32) - eb;   // stale epoch -> huge -> invalid
                    val = __uint_as_float((unsigned)(v & 0xFFFFFFFFULL));
                } else {
                    d = 2u; val = 0.f;
                }
                unsigned pm = __ballot_sync(0xFFFFFFFFu, d == 2u);
                unsigned am = __ballot_sync(0xFFFFFFFFu, d == 1u || d == 2u);
                if (pm) {
                    int p = __ffs(pm) - 1;   // closest predecessor with a full prefix
                    unsigned need = (p == 31) ? 0xFFFFFFFFu : ((1u << (p + 1)) - 1u);
                    if ((am & need) == need) {
                        float contrib = (lane <= p) ? val : 0.f;
                        #pragma unroll
                        for (int o = 16; o; o >>= 1)
                            contrib += __shfl_xor_sync(0xFFFFFFFFu, contrib, o);
                        excl += contrib;
                        break;
                    }
                } else if (am == 0xFFFFFFFFu) {
                    float contrib = val;     // window of 32 aggregates, keep walking
                    #pragma unroll
                    for (int o = 16; o; o >>= 1)
                        contrib += __shfl_xor_sync(0xFFFFFFFFu, contrib, o);
                    excl += contrib;
                    look -= 32;
                }
                // else: spin until predecessors publish
            }
            if (lane == 0)
                atomicExch(&g_state[tile], pack_sv(eb + 2u, excl + block_agg));
        }
        if (lane == 0) s_excl = excl;
    }

    // ---- stage tile-local results to skewed smem (overlaps lookback) ----
    #pragma unroll
    for (int j = 0; j < ITEMS; j++)
        s_out[SIDX(tid * ITEMS + j)] = thread_excl + vals[j];
    __syncthreads();

    const float ofs = origin + s_excl;

    // ---- coalesced, aligned store of out[base+1 .. base+remaining] ----
    if (remaining >= TILE) {
        float* op = out + base;                 // 16B-aligned (base % 8192 == 0)
        if (tid < 3)  op[1 + tid] = ofs + s_out[SIDX(tid)];       // head: out[base+1..3]
        if (tid == 3) op[TILE]    = ofs + s_out[SIDX(TILE - 1)];  // tail: out[base+TILE]
        float4* o4 = (float4*)(op + 4);         // 16B-aligned
        const int NV = (TILE - 4) / 4;          // 2047 vectors covering smem i = 3..8190
        for (int v = tid; v < NV; v += THREADS) {
            int i = 3 + 4 * v;
            float4 r;
            r.x = ofs + s_out[SIDX(i + 0)];
            r.y = ofs + s_out[SIDX(i + 1)];
            r.z = ofs + s_out[SIDX(i + 2)];
            r.w = ofs + s_out[SIDX(i + 3)];
            o4[v] = r;
        }
    } else {
        for (int i = tid; i < remaining; i += THREADS)
            out[base + 1 + i] = ofs + s_out[SIDX(i)];
    }

    if (tile == 0 && tid == 0) out[0] = origin;
}

extern "C" void kernel_launch(void* const* d_in, const int* in_sizes, int n_in,
                              void* d_out, int out_size) {
    const int*   ann    = (const int*)d_in[0];
    const float* origin = (const float*)d_in[1];
    const float* bd     = (const float*)d_in[2];
    const float* d      = (const float*)d_in[3];
    const float* s      = (const float*)d_in[4];
    const float* inc    = (const float*)d_in[5];
    const float* bi     = (const float*)d_in[6];
    float* out = (float*)d_out;

    int n = in_sizes[0];
    int ntiles = (n + TILE - 1) / TILE;
    if (ntiles > MAX_TILES) ntiles = MAX_TILES;   // n = 2^25 -> 4096 tiles

    rtam_scan<<<ntiles, THREADS>>>(ann, origin, bd, d, s, inc, bi, out, n, ntiles);
}